// round 2
// baseline (speedup 1.0000x reference)
#include <cuda_runtime.h>

#define NNODE 131072
#define NEDGE 2097152
#define BATCH 64
#define NPG   2048
#define KDIM  20480   // N * CS
#define HID   512

// ---------------- scratch (device globals; no allocation) ----------------
__device__ __align__(16) float g_deg[NNODE];          // degree -> dinv (in place)
__device__ __align__(16) float g_wn[NEDGE];           // normalized edge weights
__device__ __align__(16) float g_T0[NNODE * 20];      // [node][ch]  ch 0..9 real, 10..19 imag
__device__ __align__(16) float g_B1[NNODE * 20];      // S1 -> T1 (in place)
__device__ __align__(16) float g_B2[NNODE * 20];      // S2
__device__ __align__(16) float g_zr[BATCH * KDIM];    // fc1 input, real  [b][k]
__device__ __align__(16) float g_zi[BATCH * KDIM];    // fc1 input, imag
__device__ __align__(16) float g_accU[2 * BATCH * HID]; // GEMM partial accum: [ur | ui]
__device__ __align__(16) float g_cat[BATCH * 2 * HID];  // [b][ur(512) ui(512)]

// ---------------- helpers ----------------
__device__ __forceinline__ void red4(float* p, float a, float b, float c, float d) {
    asm volatile("red.global.add.v4.f32 [%0], {%1,%2,%3,%4};"
                 :: "l"(p), "f"(a), "f"(b), "f"(c), "f"(d) : "memory");
}
__device__ __forceinline__ void fma2(unsigned long long& d,
                                     unsigned long long a, unsigned long long b) {
    asm("fma.rn.f32x2 %0, %1, %2, %3;" : "=l"(d) : "l"(a), "l"(b), "l"(d));
}

// ---------------- stage 0: degree / dinv / wn ----------------
__global__ void k_zdeg() {
    int i = blockIdx.x * 256 + threadIdx.x;
    g_deg[i] = 0.f;
}
__global__ void k_deg(const int* __restrict__ row, const float* __restrict__ ew) {
    int e = blockIdx.x * 256 + threadIdx.x;
    atomicAdd(&g_deg[row[e]], ew[e]);
}
__global__ void k_dinv() {
    int i = blockIdx.x * 256 + threadIdx.x;
    float d = g_deg[i];
    g_deg[i] = (d > 0.f) ? rsqrtf(d + 1e-6f) : 0.f;
}
__global__ void k_wn(const int* __restrict__ row, const int* __restrict__ col,
                     const float* __restrict__ ew) {
    int e = blockIdx.x * 256 + threadIdx.x;
    g_wn[e] = ew[e] * g_deg[row[e]] * g_deg[col[e]];
}

// ---------------- stage 1: conv1 (complex 1x1 conv) + relu -> T0; zero B1 ----------------
__global__ __launch_bounds__(256) void k_conv(const float* __restrict__ xr,
                                              const float* __restrict__ xi,
                                              const float* __restrict__ wr,
                                              const float* __restrict__ wi,
                                              const float* __restrict__ br,
                                              const float* __restrict__ bi) {
    __shared__ float swr[100], swi[100], sbr[10], sbi[10];
    int t = threadIdx.x;
    if (t < 100) { swr[t] = wr[t]; swi[t] = wi[t]; }
    if (t < 10)  { sbr[t] = br[t]; sbi[t] = bi[t]; }
    __syncthreads();
    int n = blockIdx.x * 256 + t;
    float a[10], b_[10];
#pragma unroll
    for (int k = 0; k < 10; k++) { a[k] = xr[n * 10 + k]; b_[k] = xi[n * 10 + k]; }
    float* o = g_T0 + n * 20;
#pragma unroll
    for (int c = 0; c < 10; c++) {
        float yr = sbr[c], yi = sbi[c];
#pragma unroll
        for (int k = 0; k < 10; k++) {
            yr += a[k] * swr[c * 10 + k] - b_[k] * swi[c * 10 + k];
            yi += a[k] * swi[c * 10 + k] + b_[k] * swr[c * 10 + k];
        }
        o[c]      = fmaxf(yr, 0.f);
        o[10 + c] = fmaxf(yi, 0.f);
    }
    float4 z4 = make_float4(0.f, 0.f, 0.f, 0.f);
    float4* b1 = (float4*)(g_B1 + n * 20);
#pragma unroll
    for (int j = 0; j < 5; j++) b1[j] = z4;
}

// ---------------- edge scatter: S += wn * X[col]  (phase 0: T0->B1, phase 1: B1->B2) ----------------
__global__ __launch_bounds__(256) void k_scatter(const int* __restrict__ row,
                                                 const int* __restrict__ col,
                                                 int phase) {
    int e = blockIdx.x * 256 + threadIdx.x;
    int r = row[e], c = col[e];
    float w = g_wn[e];
    const float* X = (phase == 0) ? g_T0 : g_B1;
    float* S = (phase == 0) ? g_B1 : g_B2;
    const float4* xc = (const float4*)(X + c * 20);
    float* sr = S + r * 20;
#pragma unroll
    for (int j = 0; j < 5; j++) {
        float4 v = xc[j];
        red4(sr + j * 4, w * v.x, w * v.y, w * v.z, w * v.w);
    }
}

// ---------------- pointwise: T1 = T0 - S1 (into B1); zero B2 ----------------
__global__ void k_t1() {
    int i = blockIdx.x * 256 + threadIdx.x;  // over NN*5 float4
    float4 t0 = ((const float4*)g_T0)[i];
    float4 s  = ((const float4*)g_B1)[i];
    ((float4*)g_B1)[i] = make_float4(t0.x - s.x, t0.y - s.y, t0.z - s.z, t0.w - s.w);
    ((float4*)g_B2)[i] = make_float4(0.f, 0.f, 0.f, 0.f);
}

// ---------------- cheb combine: T2 = 2*(T1-S2)-T0; z = relu(sum_k Tk @ Wk (+b real)) ----------------
__global__ __launch_bounds__(256) void k_cheb(const float* __restrict__ cw,
                                              const float* __restrict__ cb) {
    __shared__ float scw[300], scb[10];
    int t = threadIdx.x;
    for (int i = t; i < 300; i += 256) scw[i] = cw[i];
    if (t < 10) scb[t] = cb[t];
    __syncthreads();
    int n = blockIdx.x * 256 + t;
    float t0[20], t1[20], t2[20];
#pragma unroll
    for (int j = 0; j < 20; j++) {
        t0[j] = g_T0[n * 20 + j];
        t1[j] = g_B1[n * 20 + j];
        t2[j] = 2.f * (t1[j] - g_B2[n * 20 + j]) - t0[j];
    }
    int b = n >> 11;          // n / NPG
    int nl = n & (NPG - 1);
    int base = b * KDIM + nl * 10;
#pragma unroll
    for (int o = 0; o < 10; o++) {
        float ar = scb[o], ai = 0.f;
#pragma unroll
        for (int i2 = 0; i2 < 10; i2++) {
            float w0 = scw[i2 * 10 + o], w1 = scw[100 + i2 * 10 + o], w2 = scw[200 + i2 * 10 + o];
            ar += t0[i2] * w0 + t1[i2] * w1 + t2[i2] * w2;
            ai += t0[10 + i2] * w0 + t1[10 + i2] * w1 + t2[10 + i2] * w2;
        }
        g_zr[base + o] = fmaxf(ar, 0.f);
        g_zi[base + o] = fmaxf(ai, 0.f);
    }
}

// ---------------- zero GEMM accumulators ----------------
__global__ void k_zacc() {
    int i = blockIdx.x * 256 + threadIdx.x;
    g_accU[i] = 0.f;
}

// ---------------- fc1 complex GEMM (fp32, packed f32x2 over h-pairs, k-split) ----------------
// grid (16 h-tiles of 32, 16 k-splits of 1280), 256 threads.
__global__ __launch_bounds__(256) void k_fc1(const float* __restrict__ Wr,
                                             const float* __restrict__ Wi) {
    __shared__ float2 s_zr[16][65];   // [kk][b] duplicated (z,z)
    __shared__ float2 s_zi[16][65];
    __shared__ float2 s_wr[16][17];   // [kk][hp] = (W[2hp][k], W[2hp+1][k])
    __shared__ float2 s_wi[16][17];

    const int t = threadIdx.x;
    const int h0 = blockIdx.x * 32;
    const int kbase0 = blockIdx.y * 1280;
    const int bg = t & 31;    // b0 = bg, b1 = bg+32
    const int hpg = t >> 5;   // hp0 = hpg, hp1 = hpg+8

    unsigned long long P[2][2][4];
#pragma unroll
    for (int a = 0; a < 2; a++)
#pragma unroll
        for (int b = 0; b < 2; b++)
#pragma unroll
            for (int c = 0; c < 4; c++) P[a][b][c] = 0ULL;

    for (int kc = 0; kc < 1280; kc += 16) {
        const int kb = kbase0 + kc;
#pragma unroll
        for (int p = 0; p < 4; p++) {
            int idx = t + p * 256;
            int kk = idx & 15, b = idx >> 4;
            float vr = g_zr[b * KDIM + kb + kk];
            float vi = g_zi[b * KDIM + kb + kk];
            s_zr[kk][b] = make_float2(vr, vr);
            s_zi[kk][b] = make_float2(vi, vi);
        }
        {
            int kk = t & 15, hp = t >> 4;
            int h = h0 + 2 * hp;
            s_wr[kk][hp] = make_float2(Wr[h * KDIM + kb + kk], Wr[(h + 1) * KDIM + kb + kk]);
            s_wi[kk][hp] = make_float2(Wi[h * KDIM + kb + kk], Wi[(h + 1) * KDIM + kb + kk]);
        }
        __syncthreads();
#pragma unroll
        for (int kk = 0; kk < 16; kk++) {
            unsigned long long zr0 = *(const unsigned long long*)&s_zr[kk][bg];
            unsigned long long zr1 = *(const unsigned long long*)&s_zr[kk][bg + 32];
            unsigned long long zi0 = *(const unsigned long long*)&s_zi[kk][bg];
            unsigned long long zi1 = *(const unsigned long long*)&s_zi[kk][bg + 32];
            unsigned long long wr0 = *(const unsigned long long*)&s_wr[kk][hpg];
            unsigned long long wr1 = *(const unsigned long long*)&s_wr[kk][hpg + 8];
            unsigned long long wi0 = *(const unsigned long long*)&s_wi[kk][hpg];
            unsigned long long wi1 = *(const unsigned long long*)&s_wi[kk][hpg + 8];
            fma2(P[0][0][0], zr0, wr0); fma2(P[0][0][1], zi0, wi0);
            fma2(P[0][0][2], zr0, wi0); fma2(P[0][0][3], zi0, wr0);
            fma2(P[0][1][0], zr1, wr0); fma2(P[0][1][1], zi1, wi0);
            fma2(P[0][1][2], zr1, wi0); fma2(P[0][1][3], zi1, wr0);
            fma2(P[1][0][0], zr0, wr1); fma2(P[1][0][1], zi0, wi1);
            fma2(P[1][0][2], zr0, wi1); fma2(P[1][0][3], zi0, wr1);
            fma2(P[1][1][0], zr1, wr1); fma2(P[1][1][1], zi1, wi1);
            fma2(P[1][1][2], zr1, wi1); fma2(P[1][1][3], zi1, wr1);
        }
        __syncthreads();
    }
#pragma unroll
    for (int hh = 0; hh < 2; hh++) {
        int hp = (hh == 0) ? hpg : (hpg + 8);
        int h = h0 + 2 * hp;
#pragma unroll
        for (int bb = 0; bb < 2; bb++) {
            int b = bg + bb * 32;
            float2 p1 = *(float2*)&P[hh][bb][0];
            float2 p2 = *(float2*)&P[hh][bb][1];
            float2 p3 = *(float2*)&P[hh][bb][2];
            float2 p4 = *(float2*)&P[hh][bb][3];
            atomicAdd(&g_accU[b * HID + h],     p1.x - p2.x);
            atomicAdd(&g_accU[b * HID + h + 1], p1.y - p2.y);
            atomicAdd(&g_accU[BATCH * HID + b * HID + h],     p3.x + p4.x);
            atomicAdd(&g_accU[BATCH * HID + b * HID + h + 1], p3.y + p4.y);
        }
    }
}

// ---------------- bias + relu -> cat ----------------
__global__ void k_relu_cat(const float* __restrict__ fbr, const float* __restrict__ fbi) {
    int i = blockIdx.x * 256 + threadIdx.x;  // over 64*512
    int b = i >> 9, h = i & 511;
    g_cat[b * 1024 + h]       = fmaxf(g_accU[i] + fbr[h], 0.f);
    g_cat[b * 1024 + 512 + h] = fmaxf(g_accU[BATCH * HID + i] + fbi[h], 0.f);
}

// ---------------- heads: logits + value ----------------
__global__ __launch_bounds__(128) void k_head(const float* __restrict__ aw,
                                              const float* __restrict__ ab,
                                              const float* __restrict__ cw,
                                              const float* __restrict__ cb,
                                              float* __restrict__ out) {
    __shared__ float s[1024];
    int b = blockIdx.x;
    for (int i = threadIdx.x; i < 1024; i += 128) s[i] = g_cat[b * 1024 + i];
    __syncthreads();
    int warp = threadIdx.x >> 5, lane = threadIdx.x & 31;
    for (int o = warp; o < 33; o += 4) {
        const float* wrow = (o < 32) ? (aw + o * 1024) : cw;
        float acc = 0.f;
        for (int k = lane; k < 1024; k += 32) acc += s[k] * wrow[k];
#pragma unroll
        for (int off = 16; off; off >>= 1) acc += __shfl_down_sync(0xffffffffu, acc, off);
        if (lane == 0) {
            if (o < 32) out[b * 32 + o] = acc + ab[o];
            else        out[BATCH * 32 + b] = acc + cb[0];
        }
    }
}

// ---------------- launch ----------------
extern "C" void kernel_launch(void* const* d_in, const int* in_sizes, int n_in,
                              void* d_out, int out_size) {
    const float* xr   = (const float*)d_in[0];
    const float* xi   = (const float*)d_in[1];
    const float* ew   = (const float*)d_in[2];
    const float* c1wr = (const float*)d_in[3];
    const float* c1wi = (const float*)d_in[4];
    const float* c1br = (const float*)d_in[5];
    const float* c1bi = (const float*)d_in[6];
    const float* chw  = (const float*)d_in[7];
    const float* chb  = (const float*)d_in[8];
    const float* f1wr = (const float*)d_in[9];
    const float* f1wi = (const float*)d_in[10];
    const float* f1br = (const float*)d_in[11];
    const float* f1bi = (const float*)d_in[12];
    const float* cw   = (const float*)d_in[13];
    const float* cb   = (const float*)d_in[14];
    const float* aw   = (const float*)d_in[15];
    const float* ab   = (const float*)d_in[16];
    const int*   ei   = (const int*)d_in[17];
    const int* row = ei;
    const int* col = ei + NEDGE;
    float* out = (float*)d_out;

    k_zdeg<<<NNODE / 256, 256>>>();
    k_deg<<<NEDGE / 256, 256>>>(row, ew);
    k_dinv<<<NNODE / 256, 256>>>();
    k_wn<<<NEDGE / 256, 256>>>(row, col, ew);
    k_conv<<<NNODE / 256, 256>>>(xr, xi, c1wr, c1wi, c1br, c1bi);
    k_scatter<<<NEDGE / 256, 256>>>(row, col, 0);
    k_t1<<<(NNODE * 5) / 256, 256>>>();
    k_scatter<<<NEDGE / 256, 256>>>(row, col, 1);
    k_cheb<<<NNODE / 256, 256>>>(chw, chb);
    k_zacc<<<(2 * BATCH * HID) / 256, 256>>>();
    k_fc1<<<dim3(16, 16), 256>>>(f1wr, f1wi);
    k_relu_cat<<<(BATCH * HID) / 256, 256>>>(f1br, f1bi);
    k_head<<<BATCH, 128>>>(aw, ab, cw, cb, out);
}